// round 5
// baseline (speedup 1.0000x reference)
#include <cuda_runtime.h>
#include <cstdint>

#define NC     8                 // cluster size (CTAs)
#define T      256               // threads per CTA
#define NWARP  (T / 32)          // 8 warps
#define VPT    8                 // elements per thread: NC*T*VPT = 16384

__device__ __forceinline__ uint32_t ctarank() {
    uint32_t r; asm("mov.u32 %0, %%cluster_ctarank;" : "=r"(r)); return r;
}
__device__ __forceinline__ uint32_t smem_u32(const void* p) {
    return (uint32_t)__cvta_generic_to_shared(p);
}
__device__ __forceinline__ void mbar_init(void* mbar, uint32_t count) {
    asm volatile("mbarrier.init.shared.b64 [%0], %1;"
                 :: "r"(smem_u32(mbar)), "r"(count) : "memory");
}
// store 8 bytes into peer CTA's smem, then arrive (release) on peer's mbarrier
__device__ __forceinline__ void send_and_arrive(void* local_slot, void* local_mbar,
                                                uint32_t rank, float x, float y) {
    uint32_t slot = smem_u32(local_slot), mbar = smem_u32(local_mbar);
    uint32_t rslot, rmbar;
    asm("mapa.shared::cluster.u32 %0, %1, %2;" : "=r"(rslot) : "r"(slot), "r"(rank));
    asm("mapa.shared::cluster.u32 %0, %1, %2;" : "=r"(rmbar) : "r"(mbar), "r"(rank));
    asm volatile("st.shared::cluster.v2.f32 [%0], {%1, %2};"
                 :: "r"(rslot), "f"(x), "f"(y) : "memory");
    asm volatile("mbarrier.arrive.release.cluster.shared::cluster.b64 _, [%0];"
                 :: "r"(rmbar) : "memory");
}
__device__ __forceinline__ void mbar_wait(void* mbar, uint32_t parity) {
    uint32_t a = smem_u32(mbar);
    asm volatile(
        "{\n\t"
        ".reg .pred P;\n\t"
        "WAIT_%=:\n\t"
        "mbarrier.try_wait.parity.acquire.cluster.shared::cta.b64 P, [%0], %1, 0x989680;\n\t"
        "@!P bra WAIT_%=;\n\t"
        "}" :: "r"(a), "r"(parity) : "memory");
}

__global__ __launch_bounds__(T, 1) __cluster_dims__(NC, 1, 1)
void nll_cluster(const float4* __restrict__ pred4,
                 const float4* __restrict__ label4,
                 float* __restrict__ out, int out_size) {
    const int t = threadIdx.x;
    const unsigned lane = t & 31u;
    const unsigned wid  = t >> 5;
    const uint32_t rank = ctarank();

    __shared__ alignas(8) unsigned long long mbar1;  // all-to-all totals (count=8)
    __shared__ alignas(8) unsigned long long mbar2;  // gather to CTA0    (count=8)
    __shared__ float2 s_tot[NC];        // (ctaTotal, ctaCnt) from each CTA
    __shared__ float2 s_red[NC];        // (c partial, unused) gathered at CTA0
    __shared__ float  s_warp[NWARP];    // warp scan totals
    __shared__ float  s_rc[NWARP];      // warp cnt sums

    // ---------------- all loads issued up front (MLP = 6) -------------------
    const int g = (int)rank * T + t;
    float4 pa = pred4[g * 2 + 0];
    float4 pb = pred4[g * 2 + 1];
    float4 l0 = label4[g * 4 + 0];
    float4 l1 = label4[g * 4 + 1];
    float4 l2 = label4[g * 4 + 2];
    float4 l3 = label4[g * 4 + 3];

    // ---------------- init mbarriers; start cluster handshake early ---------
    if (t == 0) { mbar_init(&mbar1, NC); mbar_init(&mbar2, NC); }
    __syncthreads();
    asm volatile("barrier.cluster.arrive.aligned;" ::: "memory");

    float p[VPT]  = {pa.x, pa.y, pa.z, pa.w, pb.x, pb.y, pb.z, pb.w};
    float ev[VPT] = {l0.y, l0.w, l1.y, l1.w, l2.y, l2.w, l3.y, l3.w};

    // ---------------- exp + local inclusive scan + local cnt ----------------
    float r[VPT];
    float cnt = 0.f;
    {
        float run = 0.f;
        #pragma unroll
        for (int k = 0; k < VPT; k++) {
            run += __expf(p[k]);
            r[k] = run;
            cnt += ev[k];
        }
    }
    const float tot = r[VPT - 1];

    // ---------------- warp scan of thread totals + warp cnt reduce ----------
    float ws = tot;
    #pragma unroll
    for (int o = 1; o < 32; o <<= 1) {
        float n = __shfl_up_sync(0xffffffffu, ws, o);
        if (lane >= (unsigned)o) ws += n;
    }
    float wc = cnt;
    #pragma unroll
    for (int o = 16; o > 0; o >>= 1) wc += __shfl_down_sync(0xffffffffu, wc, o);
    if (lane == 31) s_warp[wid] = ws;
    if (lane == 0)  s_rc[wid]   = wc;
    __syncthreads();

    // cluster init barrier completes here (overlapped with the scan above)
    asm volatile("barrier.cluster.wait.aligned;" ::: "memory");

    if (wid == 0) {
        // cross-warp exclusive pieces + CTA cnt, then send round 1 immediately
        float w = (lane < NWARP) ? s_warp[lane] : 0.f;
        #pragma unroll
        for (int o = 1; o < NWARP; o <<= 1) {
            float n = __shfl_up_sync(0xffffffffu, w, o);
            if (lane >= (unsigned)o) w += n;
        }
        if (lane < NWARP) s_warp[lane] = w;

        float cc = (lane < NWARP) ? s_rc[lane] : 0.f;
        #pragma unroll
        for (int o = 4; o > 0; o >>= 1) cc += __shfl_down_sync(0xffffffffu, cc, o);

        const float ctaTotal = __shfl_sync(0xffffffffu, w,  NWARP - 1);
        const float ctaCnt   = __shfl_sync(0xffffffffu, cc, 0);
        if (lane < NC)
            send_and_arrive(&s_tot[rank], &mbar1, lane, ctaTotal, ctaCnt);
    }
    __syncthreads();
    const float P = (wid ? s_warp[wid - 1] : 0.f) + (ws - tot);

    // ---------------- wait for all 8 CTA totals ------------------------------
    mbar_wait(&mbar1, 0);
    float ctaExcl = 0.f;
    #pragma unroll
    for (int j = 0; j < NC; j++)
        if ((unsigned)j < rank) ctaExcl += s_tot[j].x;

    // ---------------- masked contributions (fast log) ------------------------
    const float base = ctaExcl + P;
    float c = 0.f;
    #pragma unroll
    for (int k = 0; k < VPT; k++) {
        if (ev[k] != 0.f) c += ev[k] * (p[k] - __logf(base + r[k]));
    }

    // ---------------- CTA reduce of c ----------------------------------------
    #pragma unroll
    for (int o = 16; o > 0; o >>= 1) c += __shfl_down_sync(0xffffffffu, c, o);
    if (lane == 0) s_rc[wid] = c;        // reuse s_rc
    __syncthreads();
    if (t == 0) {
        float bc = 0.f;
        #pragma unroll
        for (int w = 0; w < NWARP; w++) bc += s_rc[w];
        send_and_arrive(&s_red[rank], &mbar2, 0u, bc, 0.f);
    }

    // ---------------- CTA 0 finalizes -----------------------------------------
    if (rank == 0 && t == 0) {
        mbar_wait(&mbar2, 0);
        float cs = 0.f, ys = 0.f;
        #pragma unroll
        for (int j = 0; j < NC; j++) { cs += s_red[j].x; ys += s_tot[j].y; }
        float cost = (ys == 0.f) ? 0.f : -(cs / fmaxf(ys, 1.f));
        out[0] = cost;
        if (out_size > 1) out[1] = ys;
    }
}

extern "C" void kernel_launch(void* const* d_in, const int* in_sizes, int n_in,
                              void* d_out, int out_size) {
    const float4* pred4  = (const float4*)d_in[0];
    const float4* label4 = (const float4*)d_in[1];
    float* out = (float*)d_out;

    nll_cluster<<<NC, T>>>(pred4, label4, out, out_size);
}

// round 6
// speedup vs baseline: 1.1245x; 1.1245x over previous
#include <cuda_runtime.h>
#include <cstdint>

#define NC     8                 // cluster size (CTAs)
#define T      256               // threads per CTA
#define NWARP  (T / 32)          // 8 warps
#define VPT    8                 // elements per thread: NC*T*VPT = 16384

__device__ __forceinline__ uint32_t ctarank() {
    uint32_t r; asm("mov.u32 %0, %%cluster_ctarank;" : "=r"(r)); return r;
}
__device__ __forceinline__ uint32_t smem_u32(const void* p) {
    return (uint32_t)__cvta_generic_to_shared(p);
}
__device__ __forceinline__ void mbar_init(void* mbar, uint32_t count) {
    asm volatile("mbarrier.init.shared.b64 [%0], %1;"
                 :: "r"(smem_u32(mbar)), "r"(count) : "memory");
}
// plain DSMEM store of 2 floats into peer CTA's smem slot
__device__ __forceinline__ void st_cluster_v2(void* local_slot, uint32_t rank,
                                              float x, float y) {
    uint32_t rslot;
    asm("mapa.shared::cluster.u32 %0, %1, %2;"
        : "=r"(rslot) : "r"(smem_u32(local_slot)), "r"(rank));
    asm volatile("st.shared::cluster.v2.f32 [%0], {%1, %2};"
                 :: "r"(rslot), "f"(x), "f"(y) : "memory");
}
// store 1 float to CTA0's slot, then release-arrive on CTA0's mbarrier
__device__ __forceinline__ void send_to_cta0(void* local_slot, void* local_mbar, float x) {
    uint32_t rslot, rmbar;
    asm("mapa.shared::cluster.u32 %0, %1, %2;"
        : "=r"(rslot) : "r"(smem_u32(local_slot)), "r"(0u));
    asm("mapa.shared::cluster.u32 %0, %1, %2;"
        : "=r"(rmbar) : "r"(smem_u32(local_mbar)), "r"(0u));
    asm volatile("st.shared::cluster.f32 [%0], %1;" :: "r"(rslot), "f"(x) : "memory");
    asm volatile("mbarrier.arrive.release.cluster.shared::cluster.b64 _, [%0];"
                 :: "r"(rmbar) : "memory");
}
__device__ __forceinline__ void mbar_wait(void* mbar, uint32_t parity) {
    uint32_t a = smem_u32(mbar);
    asm volatile(
        "{\n\t"
        ".reg .pred P;\n\t"
        "WAIT_%=:\n\t"
        "mbarrier.try_wait.parity.acquire.cluster.shared::cta.b64 P, [%0], %1, 0x989680;\n\t"
        "@!P bra WAIT_%=;\n\t"
        "}" :: "r"(a), "r"(parity) : "memory");
}

__global__ __launch_bounds__(T, 1) __cluster_dims__(NC, 1, 1)
void nll_cluster(const float4* __restrict__ pred4,
                 const float4* __restrict__ label4,
                 float* __restrict__ out, int out_size) {
    const int t = threadIdx.x;
    const unsigned lane = t & 31u;
    const unsigned wid  = t >> 5;
    const uint32_t rank = ctarank();

    __shared__ alignas(8) unsigned long long mbar2;  // gather to CTA0 (count=NC)
    __shared__ float2 s_tot[NC];        // (ctaTotal, ctaCnt) from each CTA
    __shared__ float  s_red[NC];        // partial c gathered at CTA0
    __shared__ float  s_warp[NWARP];    // warp scan totals
    __shared__ float  s_rc[NWARP];      // warp cnt / c sums

    // ---------------- all loads issued up front (MLP = 6) -------------------
    const int g = (int)rank * T + t;
    float4 pa = pred4[g * 2 + 0];
    float4 pb = pred4[g * 2 + 1];
    float4 l0 = label4[g * 4 + 0];
    float4 l1 = label4[g * 4 + 1];
    float4 l2 = label4[g * 4 + 2];
    float4 l3 = label4[g * 4 + 3];

    if (t == 0) mbar_init(&mbar2, NC);   // visibility ordered by cluster.sync below

    float p[VPT]  = {pa.x, pa.y, pa.z, pa.w, pb.x, pb.y, pb.z, pb.w};
    float ev[VPT] = {l0.y, l0.w, l1.y, l1.w, l2.y, l2.w, l3.y, l3.w};

    // ---------------- exp + local inclusive scan + local cnt ----------------
    float r[VPT];
    float cnt = 0.f;
    {
        float run = 0.f;
        #pragma unroll
        for (int k = 0; k < VPT; k++) {
            run += __expf(p[k]);
            r[k] = run;
            cnt += ev[k];
        }
    }
    const float tot = r[VPT - 1];

    // ---------------- warp scan of totals + warp reduce of cnt --------------
    float ws = tot;
    #pragma unroll
    for (int o = 1; o < 32; o <<= 1) {
        float n = __shfl_up_sync(0xffffffffu, ws, o);
        if (lane >= (unsigned)o) ws += n;
    }
    float wc = cnt;
    #pragma unroll
    for (int o = 16; o > 0; o >>= 1) wc += __shfl_down_sync(0xffffffffu, wc, o);
    if (lane == 31) s_warp[wid] = ws;
    if (lane == 0)  s_rc[wid]   = wc;
    __syncthreads();

    // ---------------- cross-warp scan + round-1 send (warp 0) ---------------
    if (wid == 0) {
        float w = (lane < NWARP) ? s_warp[lane] : 0.f;
        #pragma unroll
        for (int o = 1; o < NWARP; o <<= 1) {
            float n = __shfl_up_sync(0xffffffffu, w, o);
            if (lane >= (unsigned)o) w += n;
        }
        if (lane < NWARP) s_warp[lane] = w;

        float cc = (lane < NWARP) ? s_rc[lane] : 0.f;
        #pragma unroll
        for (int o = 4; o > 0; o >>= 1) cc += __shfl_down_sync(0xffffffffu, cc, o);

        const float ctaTotal = __shfl_sync(0xffffffffu, w,  NWARP - 1);
        const float ctaCnt   = __shfl_sync(0xffffffffu, cc, 0);
        if (lane < NC)
            st_cluster_v2(&s_tot[rank], lane, ctaTotal, ctaCnt);
    }
    __syncthreads();
    const float P = (wid ? s_warp[wid - 1] : 0.f) + (ws - tot);

    // ---------------- single cluster barrier (round 1) ----------------------
    asm volatile("barrier.cluster.arrive.aligned;" ::: "memory");
    asm volatile("barrier.cluster.wait.aligned;"   ::: "memory");

    float ctaExcl = 0.f;
    #pragma unroll
    for (int j = 0; j < NC; j++)
        if ((unsigned)j < rank) ctaExcl += s_tot[j].x;

    // ---------------- masked contributions (fast log) -----------------------
    const float base = ctaExcl + P;
    float c = 0.f;
    #pragma unroll
    for (int k = 0; k < VPT; k++) {
        if (ev[k] != 0.f) c += ev[k] * (p[k] - __logf(base + r[k]));
    }

    // ---------------- CTA reduce of c ----------------------------------------
    #pragma unroll
    for (int o = 16; o > 0; o >>= 1) c += __shfl_down_sync(0xffffffffu, c, o);
    if (lane == 0) s_rc[wid] = c;        // reuse
    __syncthreads();
    if (t == 0) {
        float bc = 0.f;
        #pragma unroll
        for (int w = 0; w < NWARP; w++) bc += s_rc[w];
        send_to_cta0(&s_red[rank], &mbar2, bc);   // only CTA0 will wait

        // ---------------- CTA 0 finalizes ------------------------------------
        if (rank == 0) {
            mbar_wait(&mbar2, 0);
            float cs = 0.f, ys = 0.f;
            #pragma unroll
            for (int j = 0; j < NC; j++) { cs += s_red[j]; ys += s_tot[j].y; }
            float cost = (ys == 0.f) ? 0.f : -(cs / fmaxf(ys, 1.f));
            out[0] = cost;
            if (out_size > 1) out[1] = ys;
        }
    }
}

extern "C" void kernel_launch(void* const* d_in, const int* in_sizes, int n_in,
                              void* d_out, int out_size) {
    const float4* pred4  = (const float4*)d_in[0];
    const float4* label4 = (const float4*)d_in[1];
    float* out = (float*)d_out;

    nll_cluster<<<NC, T>>>(pred4, label4, out, out_size);
}